// round 6
// baseline (speedup 1.0000x reference)
#include <cuda_runtime.h>
#include <math.h>

#define N_NODES 8192
#define SEQ 256
#define H 32
#define G4 128
#define NPB 4
#define NE 262144

typedef unsigned long long ull;

__device__ float g_h2[N_NODES * H];
__device__ float g_hW[N_NODES * H];
__device__ float g_agg[N_NODES * H];
__device__ float g_dinv[N_NODES];

// ---------------- packed fp32x2 + HW tanh helpers ----------------
__device__ __forceinline__ void ffma2(ull& d, ull a, ull b) {
    asm("fma.rn.f32x2 %0, %1, %2, %0;" : "+l"(d) : "l"(a), "l"(b));
}
__device__ __forceinline__ void fadd2(ull& d, ull a) {
    asm("add.rn.f32x2 %0, %0, %1;" : "+l"(d) : "l"(a));
}
__device__ __forceinline__ ull pack2(float lo, float hi) {
    ull r; asm("mov.b64 %0, {%1, %2};" : "=l"(r) : "f"(lo), "f"(hi)); return r;
}
__device__ __forceinline__ float2 unpack2(ull v) {
    float2 r; asm("mov.b64 {%0, %1}, %2;" : "=f"(r.x), "=f"(r.y) : "l"(v)); return r;
}
__device__ __forceinline__ float tanhap(float x) {
    float r; asm("tanh.approx.f32 %0, %1;" : "=f"(r) : "f"(x)); return r;
}

// =====================================================================
// Fused 2-layer LSTM + LayerNorm. 128 thr/block, 4 nodes/block,
// target 4 blocks/SM. Thread j owns z-row j; weights in regs (FFMA2).
// 3 barriers/step; LN via paired fp32x2 shfl reduction.
// =====================================================================
__global__ void __launch_bounds__(128, 4) lstm_kernel(
    const float* __restrict__ x,
    const float* __restrict__ Wih1, const float* __restrict__ Whh1,
    const float* __restrict__ bih1, const float* __restrict__ bhh1,
    const float* __restrict__ ln_g, const float* __restrict__ ln_b,
    const float* __restrict__ Wih2, const float* __restrict__ Whh2,
    const float* __restrict__ bih2, const float* __restrict__ bhh2)
{
    __shared__ __align__(16) float xs[NPB][SEQ];
    __shared__ __align__(16) float h1s[NPB][H];
    __shared__ __align__(16) float h2s[NPB][H];
    __shared__ __align__(16) float ys[NPB][H];
    __shared__ __align__(16) float z1s[NPB][G4];
    __shared__ __align__(16) float z2s[NPB][G4];
    __shared__ float lngb[2 * H];

    const int tid  = threadIdx.x;
    const int j    = tid;
    const int base = blockIdx.x * NPB;

    ull w1p[H / 2], wi2p[H / 2], wh2p[H / 2];
    {
        const ull* r1 = (const ull*)(Whh1 + j * H);
        const ull* r2 = (const ull*)(Wih2 + j * H);
        const ull* r3 = (const ull*)(Whh2 + j * H);
#pragma unroll
        for (int k2 = 0; k2 < H / 2; k2++) {
            w1p[k2] = __ldg(r1 + k2); wi2p[k2] = __ldg(r2 + k2); wh2p[k2] = __ldg(r3 + k2);
        }
    }
    const float b1j = bih1[j] + bhh1[j];
    const float b2j = bih2[j] + bhh2[j];
    const float wx1 = Wih1[j];
    const int   gate = j >> 5;                // uniform per warp
    // act(z) = mA * tanh(mS*z) + mB  (tanh for g-gate, sigmoid otherwise)
    const float mS = (gate == 2) ? 1.0f : 0.5f;
    const float mA = (gate == 2) ? 1.0f : 0.5f;
    const float mB = (gate == 2) ? 0.0f : 0.5f;

    const int m_u = tid >> 5;
    const int u   = tid & 31;
    float c1 = 0.f, c2 = 0.f;

    for (int idx = tid; idx < NPB * SEQ; idx += 128) {
        int m = idx >> 8, t = idx & 255;
        xs[m][t] = x[(base + m) * SEQ + t];
    }
    if (tid < H)          lngb[tid] = ln_g[tid];
    else if (tid < 2 * H) lngb[tid] = ln_b[tid - H];
    h1s[m_u][u] = 0.f;
    h2s[m_u][u] = 0.f;
#pragma unroll
    for (int m = 0; m < NPB; m++) z2s[m][tid] = 0.f;
    __syncthreads();

    for (int t = 0; t < SEQ; t++) {
        // ---- PhaseA: cell update 2 (t-1) ----
        {
            float gi = z2s[m_u][u];
            float gf = z2s[m_u][H + u];
            float gg = z2s[m_u][2 * H + u];
            float go = z2s[m_u][3 * H + u];
            c2 = fmaf(gf, c2, gi * gg);
            h2s[m_u][u] = go * tanhap(c2);
        }
        // ---- PhaseA: LSTM1 matvec + activation ----
        {
            ull acc[NPB];
#pragma unroll
            for (int m = 0; m < NPB; m++) acc[m] = pack2(fmaf(xs[m][t], wx1, b1j), 0.f);
#pragma unroll
            for (int k4 = 0; k4 < H / 4; k4++)
#pragma unroll
                for (int m = 0; m < NPB; m++) {
                    ulonglong2 hv = *(const ulonglong2*)&h1s[m][k4 * 4];
                    ffma2(acc[m], w1p[2 * k4], hv.x);
                    ffma2(acc[m], w1p[2 * k4 + 1], hv.y);
                }
#pragma unroll
            for (int m = 0; m < NPB; m++) {
                float2 p = unpack2(acc[m]);
                z1s[m][j] = fmaf(mA, tanhap(mS * (p.x + p.y)), mB);
            }
        }
        __syncthreads();

        // ---- PhaseB: cell update 1 + LayerNorm (paired shfl reduction) ----
        {
            float gi = z1s[m_u][u];
            float gf = z1s[m_u][H + u];
            float gg = z1s[m_u][2 * H + u];
            float go = z1s[m_u][3 * H + u];
            c1 = fmaf(gf, c1, gi * gg);
            float h = go * tanhap(c1);

            ull sv = pack2(h, h * h);
#pragma unroll
            for (int off = 16; off; off >>= 1)
                fadd2(sv, __shfl_xor_sync(0xffffffffu, sv, off));
            float2 s = unpack2(sv);
            float mu  = s.x * (1.0f / H);
            float var = fmaf(-mu, mu, s.y * (1.0f / H));
            float y = fmaf((h - mu) * rsqrtf(var + 1e-5f), lngb[u], lngb[H + u]);
            h1s[m_u][u] = h;
            ys[m_u][u]  = y;
        }
        __syncthreads();

        // ---- PhaseC: LSTM2 matvec + activation ----
        {
            ull acc[NPB];
#pragma unroll
            for (int m = 0; m < NPB; m++) acc[m] = pack2(b2j, 0.f);
#pragma unroll
            for (int k4 = 0; k4 < H / 4; k4++)
#pragma unroll
                for (int m = 0; m < NPB; m++) {
                    ulonglong2 yv = *(const ulonglong2*)&ys[m][k4 * 4];
                    ulonglong2 hv = *(const ulonglong2*)&h2s[m][k4 * 4];
                    ffma2(acc[m], wi2p[2 * k4], yv.x);
                    ffma2(acc[m], wi2p[2 * k4 + 1], yv.y);
                    ffma2(acc[m], wh2p[2 * k4], hv.x);
                    ffma2(acc[m], wh2p[2 * k4 + 1], hv.y);
                }
#pragma unroll
            for (int m = 0; m < NPB; m++) {
                float2 p = unpack2(acc[m]);
                z2s[m][j] = fmaf(mA, tanhap(mS * (p.x + p.y)), mB);
            }
        }
        __syncthreads();
    }

    // final cell update 2 -> h2 output
    {
        float gi = z2s[m_u][u];
        float gf = z2s[m_u][H + u];
        float gg = z2s[m_u][2 * H + u];
        float go = z2s[m_u][3 * H + u];
        c2 = fmaf(gf, c2, gi * gg);
        g_h2[(base + m_u) * H + u] = go * tanhap(c2);
    }
}

// =====================================================================
// GCN stage (unchanged — ~2% of runtime)
// =====================================================================
__global__ void dinv_init_kernel() {
    int i = blockIdx.x * blockDim.x + threadIdx.x;
    if (i < N_NODES) g_dinv[i] = 1.0f;
}
__global__ void deg_acc_kernel(const int* __restrict__ ei, const float* __restrict__ ew) {
    int e = blockIdx.x * blockDim.x + threadIdx.x;
    if (e < NE) atomicAdd(&g_dinv[ei[NE + e]], ew[e]);
}
__global__ void dinv_fin_kernel() {
    int i = blockIdx.x * blockDim.x + threadIdx.x;
    if (i < N_NODES) g_dinv[i] = rsqrtf(g_dinv[i]);
}

__global__ void gcn_pre_kernel(const float* __restrict__ inp, const float* __restrict__ Wg,
                               const float* __restrict__ bprev, int apply_elu)
{
    __shared__ float Ws[H * H];
    __shared__ float rows[8][H];
    int tid = threadIdx.x;
    int m = tid >> 5, u = tid & 31;
    int n = blockIdx.x * 8 + m;
    for (int i = tid; i < H * H; i += 256) Ws[i] = Wg[i];
    float v = inp[n * H + u];
    if (apply_elu) { v += bprev[u]; v = v > 0.f ? v : expm1f(v); }
    rows[m][u] = v;
    __syncthreads();
    float acc = 0.f;
#pragma unroll
    for (int k = 0; k < H; k++) acc = fmaf(rows[m][k], Ws[k * H + u], acc);
    float di = g_dinv[n];
    g_hW[n * H + u]  = acc;
    g_agg[n * H + u] = acc * di * di;
}

__global__ void gcn_scatter_kernel(const int* __restrict__ ei, const float* __restrict__ ew)
{
    int idx = blockIdx.x * blockDim.x + threadIdx.x;
    int e = idx >> 5, u = idx & 31;
    int s = ei[e];
    int d = ei[NE + e];
    float nrm = g_dinv[s] * ew[e] * g_dinv[d];
    atomicAdd(&g_agg[d * H + u], nrm * g_hW[s * H + u]);
}

__global__ void final_kernel(const float* __restrict__ bg2, const float* __restrict__ Wfc,
                             const float* __restrict__ bfc, float* __restrict__ out)
{
    int tid = threadIdx.x;
    int m = tid >> 5, u = tid & 31;
    int n = blockIdx.x * 8 + m;
    float g = g_agg[n * H + u] + bg2[u];
    g = g > 0.f ? g : expm1f(g);
    float s = g;
#pragma unroll
    for (int off = 16; off; off >>= 1) s += __shfl_xor_sync(0xffffffffu, s, off);
    float mean = s * (1.0f / H);
    float h2u = g_h2[n * H + u];
    float p0 = h2u * Wfc[u];
    float p1 = h2u * Wfc[33 + u];
#pragma unroll
    for (int off = 16; off; off >>= 1) {
        p0 += __shfl_xor_sync(0xffffffffu, p0, off);
        p1 += __shfl_xor_sync(0xffffffffu, p1, off);
    }
    if (u == 0) {
        float o0 = p0 + mean * Wfc[32]      + bfc[0];
        float o1 = p1 + mean * Wfc[33 + 32] + bfc[1];
        float mx = fmaxf(o0, o1);
        float lse = mx + logf(expf(o0 - mx) + expf(o1 - mx));
        out[n * 2 + 0] = o0 - lse;
        out[n * 2 + 1] = o1 - lse;
    }
}

// =====================================================================
extern "C" void kernel_launch(void* const* d_in, const int* in_sizes, int n_in,
                              void* d_out, int out_size)
{
    const float* x    = (const float*)d_in[0];
    const float* ew   = (const float*)d_in[1];
    const float* Wih1 = (const float*)d_in[2];
    const float* Whh1 = (const float*)d_in[3];
    const float* bih1 = (const float*)d_in[4];
    const float* bhh1 = (const float*)d_in[5];
    const float* lng  = (const float*)d_in[6];
    const float* lnb  = (const float*)d_in[7];
    const float* Wih2 = (const float*)d_in[8];
    const float* Whh2 = (const float*)d_in[9];
    const float* bih2 = (const float*)d_in[10];
    const float* bhh2 = (const float*)d_in[11];
    const float* Wg1  = (const float*)d_in[12];
    const float* bg1  = (const float*)d_in[13];
    const float* Wg2  = (const float*)d_in[14];
    const float* bg2  = (const float*)d_in[15];
    const float* Wfc  = (const float*)d_in[16];
    const float* bfc  = (const float*)d_in[17];
    const int*   eidx = (const int*)d_in[18];
    float* out = (float*)d_out;

    lstm_kernel<<<N_NODES / NPB, 128>>>(x, Wih1, Whh1, bih1, bhh1, lng, lnb,
                                        Wih2, Whh2, bih2, bhh2);

    dinv_init_kernel<<<N_NODES / 256, 256>>>();
    deg_acc_kernel<<<NE / 256, 256>>>(eidx, ew);
    dinv_fin_kernel<<<N_NODES / 256, 256>>>();

    gcn_pre_kernel<<<N_NODES / 8, 256>>>(g_h2, Wg1, bg1, 0);
    gcn_scatter_kernel<<<(NE * 32) / 256, 256>>>(eidx, ew);

    gcn_pre_kernel<<<N_NODES / 8, 256>>>(g_agg, Wg2, bg1, 1);
    gcn_scatter_kernel<<<(NE * 32) / 256, 256>>>(eidx, ew);

    final_kernel<<<N_NODES / 8, 256>>>(bg2, Wfc, bfc, out);
}

// round 7
// speedup vs baseline: 1.0785x; 1.0785x over previous
#include <cuda_runtime.h>
#include <math.h>

#define N_NODES 8192
#define SEQ 256
#define H 32
#define G4 128
#define NPB 8
#define NE 262144

typedef unsigned long long ull;

__device__ float g_h2[N_NODES * H];
__device__ float g_hW[N_NODES * H];
__device__ float g_agg[N_NODES * H];
__device__ float g_dinv[N_NODES];

// ---------------- packed fp32x2 + HW tanh helpers ----------------
__device__ __forceinline__ void ffma2(ull& d, ull a, ull b) {
    asm("fma.rn.f32x2 %0, %1, %2, %0;" : "+l"(d) : "l"(a), "l"(b));
}
__device__ __forceinline__ void fadd2(ull& d, ull a) {
    asm("add.rn.f32x2 %0, %0, %1;" : "+l"(d) : "l"(a));
}
__device__ __forceinline__ ull pack2(float lo, float hi) {
    ull r; asm("mov.b64 %0, {%1, %2};" : "=l"(r) : "f"(lo), "f"(hi)); return r;
}
__device__ __forceinline__ float2 unpack2(ull v) {
    float2 r; asm("mov.b64 {%0, %1}, %2;" : "=f"(r.x), "=f"(r.y) : "l"(v)); return r;
}
__device__ __forceinline__ float tanhap(float x) {
    float r; asm("tanh.approx.f32 %0, %1;" : "=f"(r) : "f"(x)); return r;
}

// =====================================================================
// Fused 2-layer LSTM + LayerNorm. 128 thr/block, 8 nodes/block,
// 3 blocks/SM. Thread j owns z-row j; weights in regs (FFMA2).
// 3 barriers/step amortized over 8 nodes. Each warp's update phase
// handles 2 nodes (m_u, m_u+4) with interleaved independent LN chains.
// =====================================================================
__global__ void __launch_bounds__(128, 3) lstm_kernel(
    const float* __restrict__ x,
    const float* __restrict__ Wih1, const float* __restrict__ Whh1,
    const float* __restrict__ bih1, const float* __restrict__ bhh1,
    const float* __restrict__ ln_g, const float* __restrict__ ln_b,
    const float* __restrict__ Wih2, const float* __restrict__ Whh2,
    const float* __restrict__ bih2, const float* __restrict__ bhh2)
{
    __shared__ __align__(16) float xs[NPB][SEQ];
    __shared__ __align__(16) float h1s[NPB][H];
    __shared__ __align__(16) float h2s[NPB][H];
    __shared__ __align__(16) float ys[NPB][H];
    __shared__ __align__(16) float z1s[NPB][G4];
    __shared__ __align__(16) float z2s[NPB][G4];
    __shared__ float lngb[2 * H];

    const int tid  = threadIdx.x;
    const int j    = tid;
    const int base = blockIdx.x * NPB;

    ull w1p[H / 2], wi2p[H / 2], wh2p[H / 2];
    {
        const ull* r1 = (const ull*)(Whh1 + j * H);
        const ull* r2 = (const ull*)(Wih2 + j * H);
        const ull* r3 = (const ull*)(Whh2 + j * H);
#pragma unroll
        for (int k2 = 0; k2 < H / 2; k2++) {
            w1p[k2] = __ldg(r1 + k2); wi2p[k2] = __ldg(r2 + k2); wh2p[k2] = __ldg(r3 + k2);
        }
    }
    const float b1j = bih1[j] + bhh1[j];
    const float b2j = bih2[j] + bhh2[j];
    const float wx1 = Wih1[j];
    const int   gate = j >> 5;                // uniform per warp
    // act(z) = mA * tanh(mS*z) + mB  (tanh for g-gate, sigmoid otherwise)
    const float mS = (gate == 2) ? 1.0f : 0.5f;
    const float mA = (gate == 2) ? 1.0f : 0.5f;
    const float mB = (gate == 2) ? 0.0f : 0.5f;

    const int mA0 = tid >> 5;                 // first owned node
    const int mA1 = mA0 + 4;                  // second owned node
    const int u   = tid & 31;
    float c1a = 0.f, c2a = 0.f, c1b = 0.f, c2b = 0.f;

    for (int idx = tid; idx < NPB * SEQ; idx += 128) {
        int m = idx >> 8, t = idx & 255;
        xs[m][t] = x[(base + m) * SEQ + t];
    }
    if (tid < H)          lngb[tid] = ln_g[tid];
    else if (tid < 2 * H) lngb[tid] = ln_b[tid - H];
    h1s[mA0][u] = 0.f; h1s[mA1][u] = 0.f;
    h2s[mA0][u] = 0.f; h2s[mA1][u] = 0.f;
#pragma unroll
    for (int m = 0; m < NPB; m++) z2s[m][tid] = 0.f;
    __syncthreads();

    for (int t = 0; t < SEQ; t++) {
        // ---- PhaseA: cell update 2 (t-1), two nodes per warp ----
        {
            float gia = z2s[mA0][u], gfa = z2s[mA0][H + u];
            float gga = z2s[mA0][2 * H + u], goa = z2s[mA0][3 * H + u];
            float gib = z2s[mA1][u], gfb = z2s[mA1][H + u];
            float ggb = z2s[mA1][2 * H + u], gob = z2s[mA1][3 * H + u];
            c2a = fmaf(gfa, c2a, gia * gga);
            c2b = fmaf(gfb, c2b, gib * ggb);
            h2s[mA0][u] = goa * tanhap(c2a);
            h2s[mA1][u] = gob * tanhap(c2b);
        }
        // ---- PhaseA: LSTM1 matvec + activation (8 nodes) ----
        {
            ull acc[NPB];
#pragma unroll
            for (int m = 0; m < NPB; m++) acc[m] = pack2(fmaf(xs[m][t], wx1, b1j), 0.f);
#pragma unroll
            for (int k4 = 0; k4 < H / 4; k4++)
#pragma unroll
                for (int m = 0; m < NPB; m++) {
                    ulonglong2 hv = *(const ulonglong2*)&h1s[m][k4 * 4];
                    ffma2(acc[m], w1p[2 * k4], hv.x);
                    ffma2(acc[m], w1p[2 * k4 + 1], hv.y);
                }
#pragma unroll
            for (int m = 0; m < NPB; m++) {
                float2 p = unpack2(acc[m]);
                z1s[m][j] = fmaf(mA, tanhap(mS * (p.x + p.y)), mB);
            }
        }
        __syncthreads();

        // ---- PhaseB: cell update 1 + LayerNorm, two nodes interleaved ----
        {
            float gia = z1s[mA0][u], gfa = z1s[mA0][H + u];
            float gga = z1s[mA0][2 * H + u], goa = z1s[mA0][3 * H + u];
            float gib = z1s[mA1][u], gfb = z1s[mA1][H + u];
            float ggb = z1s[mA1][2 * H + u], gob = z1s[mA1][3 * H + u];
            c1a = fmaf(gfa, c1a, gia * gga);
            c1b = fmaf(gfb, c1b, gib * ggb);
            float ha = goa * tanhap(c1a);
            float hb = gob * tanhap(c1b);

            ull sva = pack2(ha, ha * ha);
            ull svb = pack2(hb, hb * hb);
#pragma unroll
            for (int off = 16; off; off >>= 1) {
                fadd2(sva, __shfl_xor_sync(0xffffffffu, sva, off));
                fadd2(svb, __shfl_xor_sync(0xffffffffu, svb, off));
            }
            float2 sa = unpack2(sva), sb = unpack2(svb);
            float mua  = sa.x * (1.0f / H);
            float vara = fmaf(-mua, mua, sa.y * (1.0f / H));
            float mub  = sb.x * (1.0f / H);
            float varb = fmaf(-mub, mub, sb.y * (1.0f / H));
            float g = lngb[u], b = lngb[H + u];
            h1s[mA0][u] = ha;
            h1s[mA1][u] = hb;
            ys[mA0][u] = fmaf((ha - mua) * rsqrtf(vara + 1e-5f), g, b);
            ys[mA1][u] = fmaf((hb - mub) * rsqrtf(varb + 1e-5f), g, b);
        }
        __syncthreads();

        // ---- PhaseC: LSTM2 matvec + activation (8 nodes) ----
        {
            ull acc[NPB];
#pragma unroll
            for (int m = 0; m < NPB; m++) acc[m] = pack2(b2j, 0.f);
#pragma unroll
            for (int k4 = 0; k4 < H / 4; k4++)
#pragma unroll
                for (int m = 0; m < NPB; m++) {
                    ulonglong2 yv = *(const ulonglong2*)&ys[m][k4 * 4];
                    ulonglong2 hv = *(const ulonglong2*)&h2s[m][k4 * 4];
                    ffma2(acc[m], wi2p[2 * k4], yv.x);
                    ffma2(acc[m], wi2p[2 * k4 + 1], yv.y);
                    ffma2(acc[m], wh2p[2 * k4], hv.x);
                    ffma2(acc[m], wh2p[2 * k4 + 1], hv.y);
                }
#pragma unroll
            for (int m = 0; m < NPB; m++) {
                float2 p = unpack2(acc[m]);
                z2s[m][j] = fmaf(mA, tanhap(mS * (p.x + p.y)), mB);
            }
        }
        __syncthreads();
    }

    // final cell update 2 -> h2 output (two nodes per warp)
    {
        float gia = z2s[mA0][u], gfa = z2s[mA0][H + u];
        float gga = z2s[mA0][2 * H + u], goa = z2s[mA0][3 * H + u];
        float gib = z2s[mA1][u], gfb = z2s[mA1][H + u];
        float ggb = z2s[mA1][2 * H + u], gob = z2s[mA1][3 * H + u];
        c2a = fmaf(gfa, c2a, gia * gga);
        c2b = fmaf(gfb, c2b, gib * ggb);
        g_h2[(base + mA0) * H + u] = goa * tanhap(c2a);
        g_h2[(base + mA1) * H + u] = gob * tanhap(c2b);
    }
}

// =====================================================================
// GCN stage (unchanged — ~2% of runtime)
// =====================================================================
__global__ void dinv_init_kernel() {
    int i = blockIdx.x * blockDim.x + threadIdx.x;
    if (i < N_NODES) g_dinv[i] = 1.0f;
}
__global__ void deg_acc_kernel(const int* __restrict__ ei, const float* __restrict__ ew) {
    int e = blockIdx.x * blockDim.x + threadIdx.x;
    if (e < NE) atomicAdd(&g_dinv[ei[NE + e]], ew[e]);
}
__global__ void dinv_fin_kernel() {
    int i = blockIdx.x * blockDim.x + threadIdx.x;
    if (i < N_NODES) g_dinv[i] = rsqrtf(g_dinv[i]);
}

__global__ void gcn_pre_kernel(const float* __restrict__ inp, const float* __restrict__ Wg,
                               const float* __restrict__ bprev, int apply_elu)
{
    __shared__ float Ws[H * H];
    __shared__ float rows[8][H];
    int tid = threadIdx.x;
    int m = tid >> 5, u = tid & 31;
    int n = blockIdx.x * 8 + m;
    for (int i = tid; i < H * H; i += 256) Ws[i] = Wg[i];
    float v = inp[n * H + u];
    if (apply_elu) { v += bprev[u]; v = v > 0.f ? v : expm1f(v); }
    rows[m][u] = v;
    __syncthreads();
    float acc = 0.f;
#pragma unroll
    for (int k = 0; k < H; k++) acc = fmaf(rows[m][k], Ws[k * H + u], acc);
    float di = g_dinv[n];
    g_hW[n * H + u]  = acc;
    g_agg[n * H + u] = acc * di * di;
}

__global__ void gcn_scatter_kernel(const int* __restrict__ ei, const float* __restrict__ ew)
{
    int idx = blockIdx.x * blockDim.x + threadIdx.x;
    int e = idx >> 5, u = idx & 31;
    int s = ei[e];
    int d = ei[NE + e];
    float nrm = g_dinv[s] * ew[e] * g_dinv[d];
    atomicAdd(&g_agg[d * H + u], nrm * g_hW[s * H + u]);
}

__global__ void final_kernel(const float* __restrict__ bg2, const float* __restrict__ Wfc,
                             const float* __restrict__ bfc, float* __restrict__ out)
{
    int tid = threadIdx.x;
    int m = tid >> 5, u = tid & 31;
    int n = blockIdx.x * 8 + m;
    float g = g_agg[n * H + u] + bg2[u];
    g = g > 0.f ? g : expm1f(g);
    float s = g;
#pragma unroll
    for (int off = 16; off; off >>= 1) s += __shfl_xor_sync(0xffffffffu, s, off);
    float mean = s * (1.0f / H);
    float h2u = g_h2[n * H + u];
    float p0 = h2u * Wfc[u];
    float p1 = h2u * Wfc[33 + u];
#pragma unroll
    for (int off = 16; off; off >>= 1) {
        p0 += __shfl_xor_sync(0xffffffffu, p0, off);
        p1 += __shfl_xor_sync(0xffffffffu, p1, off);
    }
    if (u == 0) {
        float o0 = p0 + mean * Wfc[32]      + bfc[0];
        float o1 = p1 + mean * Wfc[33 + 32] + bfc[1];
        float mx = fmaxf(o0, o1);
        float lse = mx + logf(expf(o0 - mx) + expf(o1 - mx));
        out[n * 2 + 0] = o0 - lse;
        out[n * 2 + 1] = o1 - lse;
    }
}

// =====================================================================
extern "C" void kernel_launch(void* const* d_in, const int* in_sizes, int n_in,
                              void* d_out, int out_size)
{
    const float* x    = (const float*)d_in[0];
    const float* ew   = (const float*)d_in[1];
    const float* Wih1 = (const float*)d_in[2];
    const float* Whh1 = (const float*)d_in[3];
    const float* bih1 = (const float*)d_in[4];
    const float* bhh1 = (const float*)d_in[5];
    const float* lng  = (const float*)d_in[6];
    const float* lnb  = (const float*)d_in[7];
    const float* Wih2 = (const float*)d_in[8];
    const float* Whh2 = (const float*)d_in[9];
    const float* bih2 = (const float*)d_in[10];
    const float* bhh2 = (const float*)d_in[11];
    const float* Wg1  = (const float*)d_in[12];
    const float* bg1  = (const float*)d_in[13];
    const float* Wg2  = (const float*)d_in[14];
    const float* bg2  = (const float*)d_in[15];
    const float* Wfc  = (const float*)d_in[16];
    const float* bfc  = (const float*)d_in[17];
    const int*   eidx = (const int*)d_in[18];
    float* out = (float*)d_out;

    lstm_kernel<<<N_NODES / NPB, 128>>>(x, Wih1, Whh1, bih1, bhh1, lng, lnb,
                                        Wih2, Whh2, bih2, bhh2);

    dinv_init_kernel<<<N_NODES / 256, 256>>>();
    deg_acc_kernel<<<NE / 256, 256>>>(eidx, ew);
    dinv_fin_kernel<<<N_NODES / 256, 256>>>();

    gcn_pre_kernel<<<N_NODES / 8, 256>>>(g_h2, Wg1, bg1, 0);
    gcn_scatter_kernel<<<(NE * 32) / 256, 256>>>(eidx, ew);

    gcn_pre_kernel<<<N_NODES / 8, 256>>>(g_agg, Wg2, bg1, 1);
    gcn_scatter_kernel<<<(NE * 32) / 256, 256>>>(eidx, ew);

    final_kernel<<<N_NODES / 8, 256>>>(bg2, Wfc, bfc, out);
}

// round 8
// speedup vs baseline: 1.0789x; 1.0004x over previous
#include <cuda_runtime.h>
#include <math.h>

#define N_NODES 8192
#define SEQ 256
#define H 32
#define G4 128
#define NPB 8
#define NE 262144

typedef unsigned long long ull;

__device__ float g_h2[N_NODES * H];
__device__ float g_hW[N_NODES * H];
__device__ float g_agg[N_NODES * H];
__device__ float g_dinv[N_NODES];

// ---------------- packed fp32x2 + HW tanh helpers ----------------
__device__ __forceinline__ void ffma2(ull& d, ull a, ull b) {
    asm("fma.rn.f32x2 %0, %1, %2, %0;" : "+l"(d) : "l"(a), "l"(b));
}
__device__ __forceinline__ void fadd2(ull& d, ull a) {
    asm("add.rn.f32x2 %0, %0, %1;" : "+l"(d) : "l"(a));
}
__device__ __forceinline__ ull pack2(float lo, float hi) {
    ull r; asm("mov.b64 %0, {%1, %2};" : "=l"(r) : "f"(lo), "f"(hi)); return r;
}
__device__ __forceinline__ float2 unpack2(ull v) {
    float2 r; asm("mov.b64 {%0, %1}, %2;" : "=f"(r.x), "=f"(r.y) : "l"(v)); return r;
}
__device__ __forceinline__ float tanhap(float x) {
    float r; asm("tanh.approx.f32 %0, %1;" : "=f"(r) : "f"(x)); return r;
}

// =====================================================================
// Fused 2-layer LSTM + LayerNorm. 128 thr/block, 8 nodes/block,
// 3 blocks/SM, 2 barriers/step via one-step skew:
//   Phase1(t): matvec1(t) [h1(t-1)] ; matvec2(t-1) [y(t-1), h2(t-2)]
//   Phase2(t): cell1(t)+LN -> h1,y ; cell2(t-1) -> h2
// =====================================================================
__global__ void __launch_bounds__(128, 3) lstm_kernel(
    const float* __restrict__ x,
    const float* __restrict__ Wih1, const float* __restrict__ Whh1,
    const float* __restrict__ bih1, const float* __restrict__ bhh1,
    const float* __restrict__ ln_g, const float* __restrict__ ln_b,
    const float* __restrict__ Wih2, const float* __restrict__ Whh2,
    const float* __restrict__ bih2, const float* __restrict__ bhh2)
{
    __shared__ __align__(16) float xs[NPB][SEQ];
    __shared__ __align__(16) float h1s[NPB][H];
    __shared__ __align__(16) float h2s[NPB][H];
    __shared__ __align__(16) float ys[NPB][H];
    __shared__ __align__(16) float z1s[NPB][G4];
    __shared__ __align__(16) float z2s[NPB][G4];
    __shared__ float lngb[2 * H];

    const int tid  = threadIdx.x;
    const int j    = tid;
    const int base = blockIdx.x * NPB;

    ull w1p[H / 2], wi2p[H / 2], wh2p[H / 2];
    {
        const ull* r1 = (const ull*)(Whh1 + j * H);
        const ull* r2 = (const ull*)(Wih2 + j * H);
        const ull* r3 = (const ull*)(Whh2 + j * H);
#pragma unroll
        for (int k2 = 0; k2 < H / 2; k2++) {
            w1p[k2] = __ldg(r1 + k2); wi2p[k2] = __ldg(r2 + k2); wh2p[k2] = __ldg(r3 + k2);
        }
    }
    const float b1j = bih1[j] + bhh1[j];
    const float b2j = bih2[j] + bhh2[j];
    const float wx1 = Wih1[j];
    const int   gate = j >> 5;                // uniform per warp
    const float mS = (gate == 2) ? 1.0f : 0.5f;
    const float mA = (gate == 2) ? 1.0f : 0.5f;
    const float mB = (gate == 2) ? 0.0f : 0.5f;

    const int mA0 = tid >> 5;
    const int mA1 = mA0 + 4;
    const int u   = tid & 31;
    float c1a = 0.f, c2a = 0.f, c1b = 0.f, c2b = 0.f;

    for (int idx = tid; idx < NPB * SEQ; idx += 128) {
        int m = idx >> 8, t = idx & 255;
        xs[m][t] = x[(base + m) * SEQ + t];
    }
    if (tid < H)          lngb[tid] = ln_g[tid];
    else if (tid < 2 * H) lngb[tid] = ln_b[tid - H];
    h1s[mA0][u] = 0.f; h1s[mA1][u] = 0.f;
    h2s[mA0][u] = 0.f; h2s[mA1][u] = 0.f;
    __syncthreads();

    for (int t = 0; t < SEQ; t++) {
        // ---- Phase1: matvec1(t) ----
        {
            ull acc[NPB];
#pragma unroll
            for (int m = 0; m < NPB; m++) acc[m] = pack2(fmaf(xs[m][t], wx1, b1j), 0.f);
#pragma unroll
            for (int k4 = 0; k4 < H / 4; k4++)
#pragma unroll
                for (int m = 0; m < NPB; m++) {
                    ulonglong2 hv = *(const ulonglong2*)&h1s[m][k4 * 4];
                    ffma2(acc[m], w1p[2 * k4], hv.x);
                    ffma2(acc[m], w1p[2 * k4 + 1], hv.y);
                }
#pragma unroll
            for (int m = 0; m < NPB; m++) {
                float2 p = unpack2(acc[m]);
                z1s[m][j] = fmaf(mA, tanhap(mS * (p.x + p.y)), mB);
            }
        }
        // ---- Phase1: matvec2(t-1) ----
        if (t) {
            ull acc[NPB];
#pragma unroll
            for (int m = 0; m < NPB; m++) acc[m] = pack2(b2j, 0.f);
#pragma unroll
            for (int k4 = 0; k4 < H / 4; k4++)
#pragma unroll
                for (int m = 0; m < NPB; m++) {
                    ulonglong2 yv = *(const ulonglong2*)&ys[m][k4 * 4];
                    ulonglong2 hv = *(const ulonglong2*)&h2s[m][k4 * 4];
                    ffma2(acc[m], wi2p[2 * k4], yv.x);
                    ffma2(acc[m], wi2p[2 * k4 + 1], yv.y);
                    ffma2(acc[m], wh2p[2 * k4], hv.x);
                    ffma2(acc[m], wh2p[2 * k4 + 1], hv.y);
                }
#pragma unroll
            for (int m = 0; m < NPB; m++) {
                float2 p = unpack2(acc[m]);
                z2s[m][j] = fmaf(mA, tanhap(mS * (p.x + p.y)), mB);
            }
        }
        __syncthreads();

        // ---- Phase2: cell1(t) + LN ----
        {
            float gia = z1s[mA0][u], gfa = z1s[mA0][H + u];
            float gga = z1s[mA0][2 * H + u], goa = z1s[mA0][3 * H + u];
            float gib = z1s[mA1][u], gfb = z1s[mA1][H + u];
            float ggb = z1s[mA1][2 * H + u], gob = z1s[mA1][3 * H + u];
            c1a = fmaf(gfa, c1a, gia * gga);
            c1b = fmaf(gfb, c1b, gib * ggb);
            float ha = goa * tanhap(c1a);
            float hb = gob * tanhap(c1b);

            ull sva = pack2(ha, ha * ha);
            ull svb = pack2(hb, hb * hb);
#pragma unroll
            for (int off = 16; off; off >>= 1) {
                fadd2(sva, __shfl_xor_sync(0xffffffffu, sva, off));
                fadd2(svb, __shfl_xor_sync(0xffffffffu, svb, off));
            }
            float2 sa = unpack2(sva), sb = unpack2(svb);
            float mua  = sa.x * (1.0f / H);
            float vara = fmaf(-mua, mua, sa.y * (1.0f / H));
            float mub  = sb.x * (1.0f / H);
            float varb = fmaf(-mub, mub, sb.y * (1.0f / H));
            float g = lngb[u], b = lngb[H + u];
            h1s[mA0][u] = ha;
            h1s[mA1][u] = hb;
            ys[mA0][u] = fmaf((ha - mua) * rsqrtf(vara + 1e-5f), g, b);
            ys[mA1][u] = fmaf((hb - mub) * rsqrtf(varb + 1e-5f), g, b);
        }
        // ---- Phase2: cell2(t-1) ----
        if (t) {
            float gia = z2s[mA0][u], gfa = z2s[mA0][H + u];
            float gga = z2s[mA0][2 * H + u], goa = z2s[mA0][3 * H + u];
            float gib = z2s[mA1][u], gfb = z2s[mA1][H + u];
            float ggb = z2s[mA1][2 * H + u], gob = z2s[mA1][3 * H + u];
            c2a = fmaf(gfa, c2a, gia * gga);
            c2b = fmaf(gfb, c2b, gib * ggb);
            h2s[mA0][u] = goa * tanhap(c2a);
            h2s[mA1][u] = gob * tanhap(c2b);
        }
        __syncthreads();
    }

    // ---- tail: matvec2(SEQ-1) + cell2(SEQ-1) -> g_h2 ----
    {
        ull acc[NPB];
#pragma unroll
        for (int m = 0; m < NPB; m++) acc[m] = pack2(b2j, 0.f);
#pragma unroll
        for (int k4 = 0; k4 < H / 4; k4++)
#pragma unroll
            for (int m = 0; m < NPB; m++) {
                ulonglong2 yv = *(const ulonglong2*)&ys[m][k4 * 4];
                ulonglong2 hv = *(const ulonglong2*)&h2s[m][k4 * 4];
                ffma2(acc[m], wi2p[2 * k4], yv.x);
                ffma2(acc[m], wi2p[2 * k4 + 1], yv.y);
                ffma2(acc[m], wh2p[2 * k4], hv.x);
                ffma2(acc[m], wh2p[2 * k4 + 1], hv.y);
            }
#pragma unroll
        for (int m = 0; m < NPB; m++) {
            float2 p = unpack2(acc[m]);
            z2s[m][j] = fmaf(mA, tanhap(mS * (p.x + p.y)), mB);
        }
    }
    __syncthreads();
    {
        float gia = z2s[mA0][u], gfa = z2s[mA0][H + u];
        float gga = z2s[mA0][2 * H + u], goa = z2s[mA0][3 * H + u];
        float gib = z2s[mA1][u], gfb = z2s[mA1][H + u];
        float ggb = z2s[mA1][2 * H + u], gob = z2s[mA1][3 * H + u];
        c2a = fmaf(gfa, c2a, gia * gga);
        c2b = fmaf(gfb, c2b, gib * ggb);
        g_h2[(base + mA0) * H + u] = goa * tanhap(c2a);
        g_h2[(base + mA1) * H + u] = gob * tanhap(c2b);
    }
}

// =====================================================================
// GCN stage
// =====================================================================
__global__ void dinv_init_kernel() {
    int i = blockIdx.x * blockDim.x + threadIdx.x;
    if (i < N_NODES) g_dinv[i] = 1.0f;
}
__global__ void deg_acc_kernel(const int* __restrict__ ei, const float* __restrict__ ew) {
    int e = blockIdx.x * blockDim.x + threadIdx.x;
    if (e < NE) atomicAdd(&g_dinv[ei[NE + e]], ew[e]);
}
__global__ void dinv_fin_kernel() {
    int i = blockIdx.x * blockDim.x + threadIdx.x;
    if (i < N_NODES) g_dinv[i] = rsqrtf(g_dinv[i]);
}

__global__ void gcn_pre_kernel(const float* __restrict__ inp, const float* __restrict__ Wg,
                               const float* __restrict__ bprev, int apply_elu)
{
    __shared__ float Ws[H * H];
    __shared__ float rows[8][H];
    int tid = threadIdx.x;
    int m = tid >> 5, u = tid & 31;
    int n = blockIdx.x * 8 + m;
    for (int i = tid; i < H * H; i += 256) Ws[i] = Wg[i];
    float v = inp[n * H + u];
    if (apply_elu) { v += bprev[u]; v = v > 0.f ? v : expm1f(v); }
    rows[m][u] = v;
    __syncthreads();
    float acc = 0.f;
#pragma unroll
    for (int k = 0; k < H; k++) acc = fmaf(rows[m][k], Ws[k * H + u], acc);
    float di = g_dinv[n];
    g_hW[n * H + u]  = acc;
    g_agg[n * H + u] = acc * di * di;
}

__global__ void gcn_scatter_kernel(const int* __restrict__ ei, const float* __restrict__ ew)
{
    int idx = blockIdx.x * blockDim.x + threadIdx.x;
    int e = idx >> 5, u = idx & 31;
    int s = ei[e];
    int d = ei[NE + e];
    float nrm = g_dinv[s] * ew[e] * g_dinv[d];
    atomicAdd(&g_agg[d * H + u], nrm * g_hW[s * H + u]);
}

__global__ void final_kernel(const float* __restrict__ bg2, const float* __restrict__ Wfc,
                             const float* __restrict__ bfc, float* __restrict__ out)
{
    int tid = threadIdx.x;
    int m = tid >> 5, u = tid & 31;
    int n = blockIdx.x * 8 + m;
    float g = g_agg[n * H + u] + bg2[u];
    g = g > 0.f ? g : expm1f(g);
    float s = g;
#pragma unroll
    for (int off = 16; off; off >>= 1) s += __shfl_xor_sync(0xffffffffu, s, off);
    float mean = s * (1.0f / H);
    float h2u = g_h2[n * H + u];
    float p0 = h2u * Wfc[u];
    float p1 = h2u * Wfc[33 + u];
#pragma unroll
    for (int off = 16; off; off >>= 1) {
        p0 += __shfl_xor_sync(0xffffffffu, p0, off);
        p1 += __shfl_xor_sync(0xffffffffu, p1, off);
    }
    if (u == 0) {
        float o0 = p0 + mean * Wfc[32]      + bfc[0];
        float o1 = p1 + mean * Wfc[33 + 32] + bfc[1];
        float mx = fmaxf(o0, o1);
        float lse = mx + logf(expf(o0 - mx) + expf(o1 - mx));
        out[n * 2 + 0] = o0 - lse;
        out[n * 2 + 1] = o1 - lse;
    }
}

// =====================================================================
extern "C" void kernel_launch(void* const* d_in, const int* in_sizes, int n_in,
                              void* d_out, int out_size)
{
    const float* x    = (const float*)d_in[0];
    const float* ew   = (const float*)d_in[1];
    const float* Wih1 = (const float*)d_in[2];
    const float* Whh1 = (const float*)d_in[3];
    const float* bih1 = (const float*)d_in[4];
    const float* bhh1 = (const float*)d_in[5];
    const float* lng  = (const float*)d_in[6];
    const float* lnb  = (const float*)d_in[7];
    const float* Wih2 = (const float*)d_in[8];
    const float* Whh2 = (const float*)d_in[9];
    const float* bih2 = (const float*)d_in[10];
    const float* bhh2 = (const float*)d_in[11];
    const float* Wg1  = (const float*)d_in[12];
    const float* bg1  = (const float*)d_in[13];
    const float* Wg2  = (const float*)d_in[14];
    const float* bg2  = (const float*)d_in[15];
    const float* Wfc  = (const float*)d_in[16];
    const float* bfc  = (const float*)d_in[17];
    const int*   eidx = (const int*)d_in[18];
    float* out = (float*)d_out;

    // degree first (independent of LSTM) — puts lstm_kernel at launch #4
    // so the fixed-skip ncu capture lands on it.
    dinv_init_kernel<<<N_NODES / 256, 256>>>();
    deg_acc_kernel<<<NE / 256, 256>>>(eidx, ew);
    dinv_fin_kernel<<<N_NODES / 256, 256>>>();

    lstm_kernel<<<N_NODES / NPB, 128>>>(x, Wih1, Whh1, bih1, bhh1, lng, lnb,
                                        Wih2, Whh2, bih2, bhh2);

    gcn_pre_kernel<<<N_NODES / 8, 256>>>(g_h2, Wg1, bg1, 0);
    gcn_scatter_kernel<<<(NE * 32) / 256, 256>>>(eidx, ew);

    gcn_pre_kernel<<<N_NODES / 8, 256>>>(g_agg, Wg2, bg1, 1);
    gcn_scatter_kernel<<<(NE * 32) / 256, 256>>>(eidx, ew);

    final_kernel<<<N_NODES / 8, 256>>>(bg2, Wfc, bfc, out);
}